// round 15
// baseline (speedup 1.0000x reference)
#include <cuda_runtime.h>
#include <cstdint>

// Problem constants
#define NPTS 200000
#define NCLS 20
#define NPROP 256
#define NPAIR 400000
#define THRESH 100

// Derived
#define WPP (NPTS / 32)                 // 6250 words per proposal
#define WORDS ((size_t)NPROP * WPP)     // 1,600,000 words

// Output layout (float32, concatenated in return order)
#define OFF_SCORES  ((size_t)0)
#define OFF_MASKS   ((size_t)256)
#define OFF_CLASSES ((size_t)(256 + (size_t)NPROP * NPTS))
#define OFF_BIAS    (OFF_CLASSES + 256)
#define OFF_PROBS   (OFF_BIAS + (size_t)NPTS * 3)

#define PAD 32   // 128B stride between per-proposal counters

// One contiguous zero-region: [bits | counts | scores | rep_x] -> single memset(0)
// rep stored as x = (NPTS-1) - n with atomicMax; zero-init == clipped empty value.
#define ZWORDS (WORDS + 3 * NPROP * PAD)
__device__ unsigned int g_zero[ZWORDS];
#define G_BITS(i)  (g_zero[i])
#define G_CNT_PTR  ((int*)(g_zero + WORDS))
#define G_SCR_PTR  ((float*)(g_zero + WORDS + NPROP * PAD))
#define G_REPX_PTR ((int*)(g_zero + WORDS + 2 * NPROP * PAD))

__device__ unsigned char g_first[NPAIR];        // per-pair first-setter verdict
__device__ int   g_segpred[NPTS];
__device__ int   g_ticket;                      // gather completion ticket

// Fast exp on FMA pipe (no MUFU). rel err ~2e-6.
__device__ __forceinline__ float fexp(float x) {
    const float MAGIC = 12582912.0f;           // 1.5 * 2^23
    float t = fmaf(x, 1.4426950408889634f, MAGIC);
    int   n = __float_as_int(t) - 0x4B400000;
    float f = fmaf(x, 1.4426950408889634f, -(t - MAGIC));
    float p = 1.3333558146e-3f;
    p = fmaf(p, f, 9.6181291076e-3f);
    p = fmaf(p, f, 5.5504108664e-2f);
    p = fmaf(p, f, 2.4022650696e-1f);
    p = fmaf(p, f, 6.9314718056e-1f);
    p = fmaf(p, f, 1.0f);
    return __int_as_float(__float_as_int(p) + (n << 23));
}

// --- sH: fused pair pass, 3-deep batched atomics: atomicOr + verdict + segmin + count ---
#define PB 1024
#define PGRIDN 148
__global__ void __launch_bounds__(PB, 1)
k_pairs(const int* __restrict__ pid, const int* __restrict__ nid) {
    __shared__ int s_max[NPROP];   // max of (NPTS-1-n)  == min of n
    __shared__ int s_cnt[NPROP];
    int tid = threadIdx.x;
    if (tid < NPROP) { s_max[tid] = 0; s_cnt[tid] = 0; }
    if (blockIdx.x == 0 && tid == 0) g_ticket = 0;
    __syncthreads();

    const int S = PGRIDN * PB;                 // 151552
    int m0 = blockIdx.x * PB + tid;
    int m1 = m0 + S;
    int m2 = m1 + S;

    // batch pair loads (independent, all in flight)
    int p0 = 0, n0 = 0, p1 = 0, n1 = 0, p2 = 0, n2 = 0;
    bool a0 = m0 < NPAIR, a1 = m1 < NPAIR, a2 = m2 < NPAIR;
    if (a0) { p0 = pid[m0]; n0 = nid[m0]; }
    if (a1) { p1 = pid[m1]; n1 = nid[m1]; }
    if (a2) { p2 = pid[m2]; n2 = nid[m2]; }

    // 3 independent global atomicOr round-trips in flight
    unsigned int w0 = 0, w1 = 0, w2 = 0, k0 = 0, k1 = 0, k2 = 0;
    if (a0) { size_t b = (size_t)p0 * NPTS + n0; k0 = 1u << (b & 31u); w0 = atomicOr(&G_BITS(b >> 5), k0); }
    if (a1) { size_t b = (size_t)p1 * NPTS + n1; k1 = 1u << (b & 31u); w1 = atomicOr(&G_BITS(b >> 5), k1); }
    if (a2) { size_t b = (size_t)p2 * NPTS + n2; k2 = 1u << (b & 31u); w2 = atomicOr(&G_BITS(b >> 5), k2); }

    unsigned char f0 = (a0 && !(w0 & k0)) ? 1 : 0;
    unsigned char f1 = (a1 && !(w1 & k1)) ? 1 : 0;
    unsigned char f2 = (a2 && !(w2 & k2)) ? 1 : 0;
    if (a0) g_first[m0] = f0;
    if (a1) g_first[m1] = f1;
    if (a2) g_first[m2] = f2;

    if (a0) atomicMax(&s_max[p0], NPTS - 1 - n0);
    if (a1) atomicMax(&s_max[p1], NPTS - 1 - n1);
    if (a2) atomicMax(&s_max[p2], NPTS - 1 - n2);
    if (f0) atomicAdd(&s_cnt[p0], 1);
    if (f1) atomicAdd(&s_cnt[p1], 1);
    if (f2) atomicAdd(&s_cnt[p2], 1);

    __syncthreads();
    if (tid < NPROP) {
        if (s_max[tid]) atomicMax(&G_REPX_PTR[tid * PAD], s_max[tid]);
        if (s_cnt[tid]) atomicAdd(&G_CNT_PTR[tid * PAD], s_cnt[tid]);
    }
}

// --- s0: scatter ones into pre-zeroed masks (idempotent, no dedupe needed) ---
__global__ void __launch_bounds__(1024)
k_ones(const int* __restrict__ pid, const int* __restrict__ nid,
       float* __restrict__ out_masks) {
    int m = blockIdx.x * blockDim.x + threadIdx.x;
    if (m >= NPAIR) return;
    int p = pid[m];
    if (G_CNT_PTR[p * PAD] > THRESH)
        out_masks[(size_t)p * NPTS + nid[m]] = 1.0f;
}

// --- sB: softmax + argmax, float4 staging, fused bias passthrough ---
__global__ void k_softmax(const float* __restrict__ logit,
                          float* __restrict__ probs_out,
                          const float* __restrict__ bias,
                          float* __restrict__ bias_out) {
    __shared__ float4 s4[256 * 5];   // 20 KB
    int tid  = threadIdx.x;
    int base = blockIdx.x * 256;

    // fused bias copy: one float4 per thread across the grid (150000 total)
    {
        int bi = base + tid;
        if (bi < NPTS * 3 / 4) ((float4*)bias_out)[bi] = ((const float4*)bias)[bi];
    }

    int count = NPTS - base;
    if (count > 256) count = 256;
    int nf4 = count * 5;

    const float4* src = (const float4*)(logit + (size_t)base * NCLS);
#pragma unroll
    for (int i = tid; i < nf4; i += 256) s4[i] = src[i];
    __syncthreads();

    if (tid < count) {
        float v[NCLS];
#pragma unroll
        for (int i = 0; i < 5; i++) {
            float4 q = s4[tid * 5 + i];
            v[4 * i + 0] = q.x; v[4 * i + 1] = q.y;
            v[4 * i + 2] = q.z; v[4 * i + 3] = q.w;
        }
        float m = v[0]; int am = 0;
#pragma unroll
        for (int i = 1; i < NCLS; i++) if (v[i] > m) { m = v[i]; am = i; }
        float e[NCLS]; float sum = 0.0f;
#pragma unroll
        for (int i = 0; i < NCLS; i++) { e[i] = fexp(v[i] - m); sum += e[i]; }
        float inv = 1.0f / sum;
#pragma unroll
        for (int i = 0; i < 5; i++) {
            float4 q;
            q.x = e[4 * i + 0] * inv; q.y = e[4 * i + 1] * inv;
            q.z = e[4 * i + 2] * inv; q.w = e[4 * i + 3] * inv;
            s4[tid * 5 + i] = q;
        }
        g_segpred[base + tid] = am;
    }
    __syncthreads();

    float4* dst = (float4*)(probs_out + (size_t)base * NCLS);
#pragma unroll
    for (int i = tid; i < nf4; i += 256) dst[i] = s4[i];
}

// --- sB: score gather, 148 blocks, 3-deep batched loads, ticketed finalize ---
#define GB 1024
#define GGRIDN 148
__global__ void __launch_bounds__(GB, 1)
k_gather(const int* __restrict__ pid, const int* __restrict__ nid,
         const float* __restrict__ probs,
         float* __restrict__ out_scores, float* __restrict__ out_classes) {
    __shared__ int   s_inst[NPROP];
    __shared__ float s_scr[NPROP];
    int tid = threadIdx.x;
    if (tid < NPROP) {
        int r = NPTS - 1 - G_REPX_PTR[tid * PAD];   // in [0, NPTS-1] always
        s_inst[tid] = g_segpred[r];
        s_scr[tid] = 0.0f;
    }
    __syncthreads();

    const int S = GGRIDN * GB;                 // 151552
    int m0 = blockIdx.x * GB + tid;
    int m1 = m0 + S;
    int m2 = m1 + S;

    int p0 = 0, n0 = 0, p1 = 0, n1 = 0, p2 = 0, n2 = 0;
    unsigned char f0 = 0, f1 = 0, f2 = 0;
    if (m0 < NPAIR) { p0 = pid[m0]; n0 = nid[m0]; f0 = g_first[m0]; }
    if (m1 < NPAIR) { p1 = pid[m1]; n1 = nid[m1]; f1 = g_first[m1]; }
    if (m2 < NPAIR) { p2 = pid[m2]; n2 = nid[m2]; f2 = g_first[m2]; }

    float v0 = 0.0f, v1 = 0.0f, v2 = 0.0f;
    if (f0) v0 = __ldg(&probs[(size_t)n0 * NCLS + s_inst[p0]]);
    if (f1) v1 = __ldg(&probs[(size_t)n1 * NCLS + s_inst[p1]]);
    if (f2) v2 = __ldg(&probs[(size_t)n2 * NCLS + s_inst[p2]]);
    if (f0) atomicAdd(&s_scr[p0], v0);
    if (f1) atomicAdd(&s_scr[p1], v1);
    if (f2) atomicAdd(&s_scr[p2], v2);

    __syncthreads();
    if (tid < NPROP && s_scr[tid] != 0.0f)
        atomicAdd(&G_SCR_PTR[tid * PAD], s_scr[tid]);

    // ticket: last block performs finalize
    __shared__ int s_last;
    __threadfence();
    __syncthreads();
    if (tid == 0) s_last = (atomicAdd(&g_ticket, 1) == gridDim.x - 1) ? 1 : 0;
    __syncthreads();
    if (s_last && tid < NPROP) {
        int c = G_CNT_PTR[tid * PAD];
        int flag = (c > THRESH) ? 1 : 0;
        int cm = c > 1 ? c : 1;
        float sc = *(volatile float*)&G_SCR_PTR[tid * PAD];
        out_scores[tid]  = flag ? (sc / (float)cm) : 0.0f;
        out_classes[tid] = flag ? (float)s_inst[tid] : -1.0f;
    }
}

extern "C" void kernel_launch(void* const* d_in, const int* in_sizes, int n_in,
                              void* d_out, int out_size) {
    const float* logit = (const float*)d_in[0];
    const float* bias  = (const float*)d_in[1];
    // d_in[2] = coord: dead
    const int* pid = (const int*)d_in[3];
    const int* nid = (const int*)d_in[4];

    float* out = (float*)d_out;
    float* out_scores  = out + OFF_SCORES;
    float* out_masks   = out + OFF_MASKS;
    float* out_classes = out + OFF_CLASSES;
    float* out_bias    = out + OFF_BIAS;
    float* out_probs   = out + OFF_PROBS;

    static cudaStream_t sH = nullptr, sB = nullptr;
    static cudaEvent_t eRoot, eP, eB;
    static void *a_zero = nullptr;
    if (!sH) {
        int loPri, hiPri;
        cudaDeviceGetStreamPriorityRange(&loPri, &hiPri);
        cudaStreamCreateWithPriority(&sH, cudaStreamNonBlocking, hiPri);
        cudaStreamCreateWithPriority(&sB, cudaStreamNonBlocking, loPri);
        cudaEventCreateWithFlags(&eRoot, cudaEventDisableTiming);
        cudaEventCreateWithFlags(&eP, cudaEventDisableTiming);
        cudaEventCreateWithFlags(&eB, cudaEventDisableTiming);
        cudaGetSymbolAddress(&a_zero, g_zero);
    }

    // fork from stream 0
    cudaEventRecord(eRoot, 0);
    cudaStreamWaitEvent(sH, eRoot, 0);
    cudaStreamWaitEvent(sB, eRoot, 0);

    // stream 0: the giant mask zero-fill starts at t=0 (no dependencies)
    cudaMemsetAsync(out_masks, 0, (size_t)NPROP * NPTS * sizeof(float), 0);

    // sH (high priority): small memset (bits+cnt+scr+repx) -> pairs
    cudaMemsetAsync(a_zero, 0, ZWORDS * 4, sH);
    k_pairs<<<PGRIDN, PB, 0, sH>>>(pid, nid);
    cudaEventRecord(eP, sH);

    // sB (low priority): softmax(+bias) -> (wait pairs) gather(+finalize)
    k_softmax<<<(NPTS + 255) / 256, 256, 0, sB>>>(logit, out_probs, bias, out_bias);
    cudaStreamWaitEvent(sB, eP, 0);
    k_gather<<<GGRIDN, GB, 0, sB>>>(pid, nid, out_probs, out_scores, out_classes);
    cudaEventRecord(eB, sB);

    // stream 0: after its memset AND pairs' counts -> scatter the ones
    cudaStreamWaitEvent(0, eP, 0);
    k_ones<<<(NPAIR + 1023) / 1024, 1024>>>(pid, nid, out_masks);

    // join gather into stream 0
    cudaStreamWaitEvent(0, eB, 0);
}

// round 17
// speedup vs baseline: 1.3748x; 1.3748x over previous
#include <cuda_runtime.h>
#include <cstdint>

// Problem constants
#define NPTS 200000
#define NCLS 20
#define NPROP 256
#define NPAIR 400000
#define THRESH 100

// Derived
#define WPP (NPTS / 32)                 // 6250 words per proposal
#define WORDS ((size_t)NPROP * WPP)     // 1,600,000 words (divisible by 256, NOT by 1024)

// Output layout (float32, concatenated in return order)
#define OFF_SCORES  ((size_t)0)
#define OFF_MASKS   ((size_t)256)
#define OFF_CLASSES ((size_t)(256 + (size_t)NPROP * NPTS))
#define OFF_BIAS    (OFF_CLASSES + 256)
#define OFF_PROBS   (OFF_BIAS + (size_t)NPTS * 3)

#define PAD 32   // 128B stride between per-proposal counters

// One contiguous zero-region: [bits | counts | scores | rep_x] -> single memset(0)
// rep stored as x = (NPTS-1) - n with atomicMax; zero-init == clipped empty value.
#define ZWORDS (WORDS + 3 * NPROP * PAD)
__device__ unsigned int g_zero[ZWORDS];
#define G_BITS(i)  (g_zero[i])
#define G_CNT_PTR  ((int*)(g_zero + WORDS))
#define G_SCR_PTR  ((float*)(g_zero + WORDS + NPROP * PAD))
#define G_REPX_PTR ((int*)(g_zero + WORDS + 2 * NPROP * PAD))

__device__ unsigned char g_first[NPAIR];        // per-pair first-setter verdict
__device__ int   g_segpred[NPTS];
__device__ int   g_ticket;                      // gather completion ticket

// Fast exp on FMA pipe (no MUFU). rel err ~2e-6.
__device__ __forceinline__ float fexp(float x) {
    const float MAGIC = 12582912.0f;           // 1.5 * 2^23
    float t = fmaf(x, 1.4426950408889634f, MAGIC);
    int   n = __float_as_int(t) - 0x4B400000;
    float f = fmaf(x, 1.4426950408889634f, -(t - MAGIC));
    float p = 1.3333558146e-3f;
    p = fmaf(p, f, 9.6181291076e-3f);
    p = fmaf(p, f, 5.5504108664e-2f);
    p = fmaf(p, f, 2.4022650696e-1f);
    p = fmaf(p, f, 6.9314718056e-1f);
    p = fmaf(p, f, 1.0f);
    return __int_as_float(__float_as_int(p) + (n << 23));
}

// --- s0: fused pair pass, 3-deep batched atomics: atomicOr + verdict + repmax + count ---
#define PB 1024
#define PGRIDN 148
__global__ void __launch_bounds__(PB, 1)
k_pairs(const int* __restrict__ pid, const int* __restrict__ nid) {
    __shared__ int s_max[NPROP];   // max of (NPTS-1-n)  == min of n
    __shared__ int s_cnt[NPROP];
    int tid = threadIdx.x;
    if (tid < NPROP) { s_max[tid] = 0; s_cnt[tid] = 0; }
    if (blockIdx.x == 0 && tid == 0) g_ticket = 0;
    __syncthreads();

    const int S = PGRIDN * PB;                 // 151552
    int m0 = blockIdx.x * PB + tid;
    int m1 = m0 + S;
    int m2 = m1 + S;

    // batch pair loads (independent, all in flight)
    int p0 = 0, n0 = 0, p1 = 0, n1 = 0, p2 = 0, n2 = 0;
    bool a0 = m0 < NPAIR, a1 = m1 < NPAIR, a2 = m2 < NPAIR;
    if (a0) { p0 = pid[m0]; n0 = nid[m0]; }
    if (a1) { p1 = pid[m1]; n1 = nid[m1]; }
    if (a2) { p2 = pid[m2]; n2 = nid[m2]; }

    // 3 independent global atomicOr round-trips in flight
    unsigned int w0 = 0, w1 = 0, w2 = 0, k0 = 0, k1 = 0, k2 = 0;
    if (a0) { size_t b = (size_t)p0 * NPTS + n0; k0 = 1u << (b & 31u); w0 = atomicOr(&G_BITS(b >> 5), k0); }
    if (a1) { size_t b = (size_t)p1 * NPTS + n1; k1 = 1u << (b & 31u); w1 = atomicOr(&G_BITS(b >> 5), k1); }
    if (a2) { size_t b = (size_t)p2 * NPTS + n2; k2 = 1u << (b & 31u); w2 = atomicOr(&G_BITS(b >> 5), k2); }

    unsigned char f0 = (a0 && !(w0 & k0)) ? 1 : 0;
    unsigned char f1 = (a1 && !(w1 & k1)) ? 1 : 0;
    unsigned char f2 = (a2 && !(w2 & k2)) ? 1 : 0;
    if (a0) g_first[m0] = f0;
    if (a1) g_first[m1] = f1;
    if (a2) g_first[m2] = f2;

    if (a0) atomicMax(&s_max[p0], NPTS - 1 - n0);
    if (a1) atomicMax(&s_max[p1], NPTS - 1 - n1);
    if (a2) atomicMax(&s_max[p2], NPTS - 1 - n2);
    if (f0) atomicAdd(&s_cnt[p0], 1);
    if (f1) atomicAdd(&s_cnt[p1], 1);
    if (f2) atomicAdd(&s_cnt[p2], 1);

    __syncthreads();
    if (tid < NPROP) {
        if (s_max[tid]) atomicMax(&G_REPX_PTR[tid * PAD], s_max[tid]);
        if (s_cnt[tid]) atomicAdd(&G_CNT_PTR[tid * PAD], s_cnt[tid]);
    }
}

// --- s0: mask expansion, warp-coalesced 512B streaming stores.
// 256-thread blocks: 6250 blocks covers WORDS exactly (grid math relies on this). ---
__global__ void k_masks(float* __restrict__ out_masks) {
    int tid = threadIdx.x;
    int t = blockIdx.x * blockDim.x + tid;   // word index (exact grid)
    int lane = tid & 31;
    int p = t / WPP;
    unsigned int w = G_BITS(t);
    if (G_CNT_PTR[p * PAD] <= THRESH) w = 0u;

    size_t warp_word0 = (size_t)(t - lane);
    float4* dst = (float4*)out_masks + warp_word0 * 8;   // 8 float4 per word
    int nib = (lane & 7) * 4;
#pragma unroll
    for (int i = 0; i < 8; i++) {
        unsigned int src = __shfl_sync(0xFFFFFFFFu, w, i * 4 + (lane >> 3));
        float4 f;
        f.x = (float)((src >> (nib + 0)) & 1u);
        f.y = (float)((src >> (nib + 1)) & 1u);
        f.z = (float)((src >> (nib + 2)) & 1u);
        f.w = (float)((src >> (nib + 3)) & 1u);
        __stcs(&dst[(size_t)i * 32 + lane], f);   // streaming: don't pollute L2
    }
}

// --- sB: softmax + argmax, float4 staging, fused bias passthrough ---
__global__ void k_softmax(const float* __restrict__ logit,
                          float* __restrict__ probs_out,
                          const float* __restrict__ bias,
                          float* __restrict__ bias_out) {
    __shared__ float4 s4[256 * 5];   // 20 KB
    int tid  = threadIdx.x;
    int base = blockIdx.x * 256;

    // fused bias copy: one float4 per thread across the grid (150000 total)
    {
        int bi = base + tid;
        if (bi < NPTS * 3 / 4) ((float4*)bias_out)[bi] = ((const float4*)bias)[bi];
    }

    int count = NPTS - base;
    if (count > 256) count = 256;
    int nf4 = count * 5;

    const float4* src = (const float4*)(logit + (size_t)base * NCLS);
#pragma unroll
    for (int i = tid; i < nf4; i += 256) s4[i] = src[i];
    __syncthreads();

    if (tid < count) {
        float v[NCLS];
#pragma unroll
        for (int i = 0; i < 5; i++) {
            float4 q = s4[tid * 5 + i];
            v[4 * i + 0] = q.x; v[4 * i + 1] = q.y;
            v[4 * i + 2] = q.z; v[4 * i + 3] = q.w;
        }
        float m = v[0]; int am = 0;
#pragma unroll
        for (int i = 1; i < NCLS; i++) if (v[i] > m) { m = v[i]; am = i; }
        float e[NCLS]; float sum = 0.0f;
#pragma unroll
        for (int i = 0; i < NCLS; i++) { e[i] = fexp(v[i] - m); sum += e[i]; }
        float inv = 1.0f / sum;
#pragma unroll
        for (int i = 0; i < 5; i++) {
            float4 q;
            q.x = e[4 * i + 0] * inv; q.y = e[4 * i + 1] * inv;
            q.z = e[4 * i + 2] * inv; q.w = e[4 * i + 3] * inv;
            s4[tid * 5 + i] = q;
        }
        g_segpred[base + tid] = am;
    }
    __syncthreads();

    float4* dst = (float4*)(probs_out + (size_t)base * NCLS);
#pragma unroll
    for (int i = tid; i < nf4; i += 256) dst[i] = s4[i];
}

// --- sB: score gather, 148 blocks, 3-deep batched loads, ticketed finalize ---
#define GB 1024
#define GGRIDN 148
__global__ void __launch_bounds__(GB, 1)
k_gather(const int* __restrict__ pid, const int* __restrict__ nid,
         const float* __restrict__ probs,
         float* __restrict__ out_scores, float* __restrict__ out_classes) {
    __shared__ int   s_inst[NPROP];
    __shared__ float s_scr[NPROP];
    int tid = threadIdx.x;
    if (tid < NPROP) {
        int r = NPTS - 1 - G_REPX_PTR[tid * PAD];   // in [0, NPTS-1] always
        s_inst[tid] = g_segpred[r];
        s_scr[tid] = 0.0f;
    }
    __syncthreads();

    const int S = GGRIDN * GB;                 // 151552
    int m0 = blockIdx.x * GB + tid;
    int m1 = m0 + S;
    int m2 = m1 + S;

    int p0 = 0, n0 = 0, p1 = 0, n1 = 0, p2 = 0, n2 = 0;
    unsigned char f0 = 0, f1 = 0, f2 = 0;
    if (m0 < NPAIR) { p0 = pid[m0]; n0 = nid[m0]; f0 = g_first[m0]; }
    if (m1 < NPAIR) { p1 = pid[m1]; n1 = nid[m1]; f1 = g_first[m1]; }
    if (m2 < NPAIR) { p2 = pid[m2]; n2 = nid[m2]; f2 = g_first[m2]; }

    float v0 = 0.0f, v1 = 0.0f, v2 = 0.0f;
    if (f0) v0 = __ldg(&probs[(size_t)n0 * NCLS + s_inst[p0]]);
    if (f1) v1 = __ldg(&probs[(size_t)n1 * NCLS + s_inst[p1]]);
    if (f2) v2 = __ldg(&probs[(size_t)n2 * NCLS + s_inst[p2]]);
    if (f0) atomicAdd(&s_scr[p0], v0);
    if (f1) atomicAdd(&s_scr[p1], v1);
    if (f2) atomicAdd(&s_scr[p2], v2);

    __syncthreads();
    if (tid < NPROP && s_scr[tid] != 0.0f)
        atomicAdd(&G_SCR_PTR[tid * PAD], s_scr[tid]);

    // ticket: last block performs finalize
    __shared__ int s_last;
    __threadfence();
    __syncthreads();
    if (tid == 0) s_last = (atomicAdd(&g_ticket, 1) == gridDim.x - 1) ? 1 : 0;
    __syncthreads();
    if (s_last && tid < NPROP) {
        int c = G_CNT_PTR[tid * PAD];
        int flag = (c > THRESH) ? 1 : 0;
        int cm = c > 1 ? c : 1;
        float sc = *(volatile float*)&G_SCR_PTR[tid * PAD];
        out_scores[tid]  = flag ? (sc / (float)cm) : 0.0f;
        out_classes[tid] = flag ? (float)s_inst[tid] : -1.0f;
    }
}

extern "C" void kernel_launch(void* const* d_in, const int* in_sizes, int n_in,
                              void* d_out, int out_size) {
    const float* logit = (const float*)d_in[0];
    const float* bias  = (const float*)d_in[1];
    // d_in[2] = coord: dead
    const int* pid = (const int*)d_in[3];
    const int* nid = (const int*)d_in[4];

    float* out = (float*)d_out;
    float* out_scores  = out + OFF_SCORES;
    float* out_masks   = out + OFF_MASKS;
    float* out_classes = out + OFF_CLASSES;
    float* out_bias    = out + OFF_BIAS;
    float* out_probs   = out + OFF_PROBS;

    static cudaStream_t sB = nullptr;
    static cudaEvent_t eRoot, eP, eB;
    static void *a_zero = nullptr;
    if (!sB) {
        int loPri, hiPri;
        cudaDeviceGetStreamPriorityRange(&loPri, &hiPri);
        cudaStreamCreateWithPriority(&sB, cudaStreamNonBlocking, loPri);
        cudaEventCreateWithFlags(&eRoot, cudaEventDisableTiming);
        cudaEventCreateWithFlags(&eP, cudaEventDisableTiming);
        cudaEventCreateWithFlags(&eB, cudaEventDisableTiming);
        cudaGetSymbolAddress(&a_zero, g_zero);
    }

    // fork sB from stream 0
    cudaEventRecord(eRoot, 0);
    cudaStreamWaitEvent(sB, eRoot, 0);

    // stream 0 (critical chain): memset -> pairs -> masks (join implicit)
    cudaMemsetAsync(a_zero, 0, ZWORDS * 4, 0);
    k_pairs<<<PGRIDN, PB>>>(pid, nid);
    cudaEventRecord(eP, 0);
    k_masks<<<(int)(WORDS / 256), 256>>>(out_masks);

    // sB (low priority): softmax(+bias) -> (wait pairs) gather(+finalize)
    k_softmax<<<(NPTS + 255) / 256, 256, 0, sB>>>(logit, out_probs, bias, out_bias);
    cudaStreamWaitEvent(sB, eP, 0);
    k_gather<<<GGRIDN, GB, 0, sB>>>(pid, nid, out_probs, out_scores, out_classes);
    cudaEventRecord(eB, sB);

    // join sB into stream 0
    cudaStreamWaitEvent(0, eB, 0);
}